// round 2
// baseline (speedup 1.0000x reference)
#include <cuda_runtime.h>
#include <math.h>

// Problem shape (fixed per reference)
constexpr int BATCH = 8;
constexpr int SEQ_T = 2048;
constexpr int D_MODEL = 1024;
constexpr int N_STATE = 1024;
constexpr int MROWS = BATCH * SEQ_T;      // 16384
constexpr int CHUNK = 128;
constexpr int NCHUNK = SEQ_T / CHUNK;     // 16

// Scratch (no cudaMalloc allowed): h / B_x buffer + chunk carries
__device__ float g_bx[MROWS * N_STATE];                 // 64 MB
__device__ float g_end[BATCH * NCHUNK * N_STATE];       // chunk-local scan ends
__device__ float g_excl[BATCH * NCHUNK * N_STATE];      // exclusive cross-chunk carry

__device__ __forceinline__ float sigmoidf_(float x) {
    return 1.0f / (1.0f + __expf(-x));
}

// ---------------------------------------------------------------------------
// SGEMM: C[M,N] = A[M,K] * B[N,K]^T + bias[N]
// Both operands K-major (row-major with K contiguous). 128x128x8 tiles,
// 256 threads, 8x8 register tile per thread.
// ---------------------------------------------------------------------------
__global__ __launch_bounds__(256) void sgemm_tn_kernel(
    const float* __restrict__ A, const float* __restrict__ Bm,
    const float* __restrict__ bias, float* __restrict__ C,
    int M, int N, int K)
{
    constexpr int BM = 128, BN = 128, BK = 8;
    __shared__ float As[BK][BM];
    __shared__ float Bs[BK][BN];

    const int tid = threadIdx.x;
    const int mBase = blockIdx.y * BM;
    const int nBase = blockIdx.x * BN;
    const int tx = tid & 15;        // 0..15 -> n
    const int ty = tid >> 4;        // 0..15 -> m

    const int ldRow = tid >> 1;     // 0..127
    const int ldCol = (tid & 1) * 4;

    const float* Aptr = A + (size_t)(mBase + ldRow) * K + ldCol;
    const float* Bptr = Bm + (size_t)(nBase + ldRow) * K + ldCol;

    float acc[8][8];
#pragma unroll
    for (int i = 0; i < 8; i++)
#pragma unroll
        for (int j = 0; j < 8; j++) acc[i][j] = 0.0f;

    for (int k0 = 0; k0 < K; k0 += BK) {
        float4 av = *reinterpret_cast<const float4*>(Aptr + k0);
        float4 bv = *reinterpret_cast<const float4*>(Bptr + k0);
        __syncthreads();
        As[ldCol + 0][ldRow] = av.x;
        As[ldCol + 1][ldRow] = av.y;
        As[ldCol + 2][ldRow] = av.z;
        As[ldCol + 3][ldRow] = av.w;
        Bs[ldCol + 0][ldRow] = bv.x;
        Bs[ldCol + 1][ldRow] = bv.y;
        Bs[ldCol + 2][ldRow] = bv.z;
        Bs[ldCol + 3][ldRow] = bv.w;
        __syncthreads();

#pragma unroll
        for (int kk = 0; kk < BK; kk++) {
            float4 a0 = *reinterpret_cast<const float4*>(&As[kk][ty * 8]);
            float4 a1 = *reinterpret_cast<const float4*>(&As[kk][ty * 8 + 4]);
            float4 b0 = *reinterpret_cast<const float4*>(&Bs[kk][tx * 8]);
            float4 b1 = *reinterpret_cast<const float4*>(&Bs[kk][tx * 8 + 4]);
            float a[8] = {a0.x, a0.y, a0.z, a0.w, a1.x, a1.y, a1.z, a1.w};
            float b[8] = {b0.x, b0.y, b0.z, b0.w, b1.x, b1.y, b1.z, b1.w};
#pragma unroll
            for (int i = 0; i < 8; i++)
#pragma unroll
                for (int j = 0; j < 8; j++)
                    acc[i][j] = fmaf(a[i], b[j], acc[i][j]);
        }
    }

    float bvals[8];
#pragma unroll
    for (int j = 0; j < 8; j++) bvals[j] = bias[nBase + tx * 8 + j];

#pragma unroll
    for (int i = 0; i < 8; i++) {
        int row = mBase + ty * 8 + i;
        float4* cp = reinterpret_cast<float4*>(C + (size_t)row * N + nBase + tx * 8);
        float4 r0, r1;
        r0.x = acc[i][0] + bvals[0];
        r0.y = acc[i][1] + bvals[1];
        r0.z = acc[i][2] + bvals[2];
        r0.w = acc[i][3] + bvals[3];
        r1.x = acc[i][4] + bvals[4];
        r1.y = acc[i][5] + bvals[5];
        r1.z = acc[i][6] + bvals[6];
        r1.w = acc[i][7] + bvals[7];
        cp[0] = r0;
        cp[1] = r1;
    }
}

// ---------------------------------------------------------------------------
// Scan stage 1: per-(b, chunk, n) local inclusive scan in place; write ends.
// ---------------------------------------------------------------------------
__global__ __launch_bounds__(256) void scan_local_kernel(const float* __restrict__ log_A)
{
    int idx = blockIdx.x * blockDim.x + threadIdx.x;   // B*NCHUNK*N threads
    int n = idx & (N_STATE - 1);
    int c = (idx / N_STATE) & (NCHUNK - 1);
    int b = idx / (N_STATE * NCHUNK);
    if (b >= BATCH) return;

    const float Av = sigmoidf_(log_A[n]);
    size_t base = ((size_t)b * SEQ_T + (size_t)c * CHUNK) * N_STATE + n;
    float h = 0.0f;
#pragma unroll 4
    for (int t = 0; t < CHUNK; t++) {
        size_t off = base + (size_t)t * N_STATE;
        h = fmaf(Av, h, g_bx[off]);
        g_bx[off] = h;
    }
    g_end[((size_t)b * NCHUNK + c) * N_STATE + n] = h;
}

// ---------------------------------------------------------------------------
// Scan stage 2: cross-chunk exclusive carry scan (16 chunks, serial per (b,n)).
// ---------------------------------------------------------------------------
__global__ __launch_bounds__(256) void scan_carry_kernel(const float* __restrict__ log_A)
{
    int idx = blockIdx.x * blockDim.x + threadIdx.x;   // B*N threads
    int n = idx & (N_STATE - 1);
    int b = idx / N_STATE;
    if (b >= BATCH) return;

    float Av = sigmoidf_(log_A[n]);
    // A^CHUNK via repeated squaring (CHUNK = 2^7)
    float aL = Av;
#pragma unroll
    for (int s = 0; s < 7; s++) aL = aL * aL;

    float E = 0.0f;
#pragma unroll
    for (int c = 0; c < NCHUNK; c++) {
        size_t off = ((size_t)b * NCHUNK + c) * N_STATE + n;
        g_excl[off] = E;
        E = fmaf(aL, E, g_end[off]);
    }
}

// ---------------------------------------------------------------------------
// Scan stage 3: fixup  h_t = local_t + A^{t+1} * carry
// ---------------------------------------------------------------------------
__global__ __launch_bounds__(256) void scan_fixup_kernel(const float* __restrict__ log_A)
{
    int idx = blockIdx.x * blockDim.x + threadIdx.x;   // B*NCHUNK*N threads
    int n = idx & (N_STATE - 1);
    int c = (idx / N_STATE) & (NCHUNK - 1);
    int b = idx / (N_STATE * NCHUNK);
    if (b >= BATCH) return;
    if (c == 0) return;   // first chunk has zero carry

    const float Av = sigmoidf_(log_A[n]);
    float E = g_excl[((size_t)b * NCHUNK + c) * N_STATE + n];
    if (E == 0.0f) return;
    float p = Av;
    size_t base = ((size_t)b * SEQ_T + (size_t)c * CHUNK) * N_STATE + n;
#pragma unroll 4
    for (int t = 0; t < CHUNK; t++) {
        size_t off = base + (size_t)t * N_STATE;
        g_bx[off] = fmaf(p, E, g_bx[off]);
        p *= Av;
    }
}

// ---------------------------------------------------------------------------
// Launch
// ---------------------------------------------------------------------------
extern "C" void kernel_launch(void* const* d_in, const int* in_sizes, int n_in,
                              void* d_out, int out_size)
{
    const float* x    = (const float*)d_in[0];   // [8, 2048, 1024]
    const float* logA = (const float*)d_in[1];   // [1024]
    const float* B_w  = (const float*)d_in[2];   // [1024, 1024] (N, D)
    const float* B_b  = (const float*)d_in[3];   // [1024]
    const float* C_w  = (const float*)d_in[4];   // [1024, 1024] (D, N)
    const float* C_b  = (const float*)d_in[5];   // [1024]
    float* y = (float*)d_out;                    // [8, 2048, 1024]

    float* bx;
    cudaGetSymbolAddress((void**)&bx, g_bx);

    // GEMM1: B_x = x @ B_w^T + B_b
    {
        dim3 grid(N_STATE / 128, MROWS / 128);
        sgemm_tn_kernel<<<grid, 256>>>(x, B_w, B_b, bx, MROWS, N_STATE, D_MODEL);
    }

    // Scan (chunked)
    {
        int total = BATCH * NCHUNK * N_STATE;
        scan_local_kernel<<<total / 256, 256>>>(logA);
        int total2 = BATCH * N_STATE;
        scan_carry_kernel<<<total2 / 256, 256>>>(logA);
        scan_fixup_kernel<<<total / 256, 256>>>(logA);
    }

    // GEMM2: y = h @ C_w^T + C_b
    {
        dim3 grid(D_MODEL / 128, MROWS / 128);
        sgemm_tn_kernel<<<grid, 256>>>(bx, C_w, C_b, y, MROWS, D_MODEL, N_STATE);
    }
}

// round 3
// speedup vs baseline: 2.0236x; 2.0236x over previous
#include <cuda_runtime.h>
#include <math.h>
#include <stdint.h>

// Problem shape (fixed per reference)
constexpr int BATCH = 8;
constexpr int SEQ_T = 2048;
constexpr int D_MODEL = 1024;
constexpr int N_STATE = 1024;
constexpr int MROWS = BATCH * SEQ_T;      // 16384
constexpr int CHUNK = 128;
constexpr int NCHUNK = SEQ_T / CHUNK;     // 16

// Scratch (no cudaMalloc allowed)
__device__ float g_bx[MROWS * N_STATE];                 // 64 MB: B_x then h in-place
__device__ float g_end[BATCH * NCHUNK * N_STATE];       // chunk-local scan end states

__device__ __forceinline__ float sigmoidf_(float x) {
    return 1.0f / (1.0f + __expf(-x));
}

__device__ __forceinline__ uint32_t f2tf32(float x) {
    uint32_t r;
    asm("cvt.rna.tf32.f32 %0, %1;" : "=r"(r) : "f"(x));
    return r;
}

// ---------------------------------------------------------------------------
// TF32 tensor-core GEMM: C[M,N] = A[M,K] * B[N,K]^T + bias[N]
// Both operands K-major. 128x128x16 tiles, 256 threads (8 warps),
// warp tile 32x64 via m16n8k8 tf32 mma.sync.
// ---------------------------------------------------------------------------
__global__ __launch_bounds__(256) void gemm_tf32_tn(
    const float* __restrict__ A, const float* __restrict__ Bm,
    const float* __restrict__ bias, float* __restrict__ C,
    int M, int N, int K)
{
    constexpr int BM = 128, BN = 128, BK = 16;
    constexpr int LDS = BK + 1;             // pad -> stride 17 floats
    __shared__ float As[BM][LDS];
    __shared__ float Bs[BN][LDS];

    const int tid  = threadIdx.x;
    const int lane = tid & 31;
    const int wid  = tid >> 5;
    const int g = lane >> 2;                // 0..7
    const int t = lane & 3;                 // 0..3

    const int warpM = (wid >> 1) * 32;      // 4 warps along M
    const int warpN = (wid & 1) * 64;       // 2 warps along N

    const int mBase = blockIdx.y * BM;
    const int nBase = blockIdx.x * BN;

    float acc[2][8][4];
#pragma unroll
    for (int mt = 0; mt < 2; mt++)
#pragma unroll
        for (int nt = 0; nt < 8; nt++)
#pragma unroll
            for (int i = 0; i < 4; i++) acc[mt][nt][i] = 0.0f;

    for (int k0 = 0; k0 < K; k0 += BK) {
        if (k0) __syncthreads();
        // ---- fill smem (convert fp32 -> tf32 bit pattern via rna) ----
#pragma unroll
        for (int i = 0; i < 2; i++) {
            int idx = tid * 2 + i;          // 0..511 float4 slots
            int row = idx >> 2;             // 0..127
            int c4  = (idx & 3) * 4;        // 0,4,8,12
            float4 av = *reinterpret_cast<const float4*>(A + (size_t)(mBase + row) * K + k0 + c4);
            float4 bv = *reinterpret_cast<const float4*>(Bm + (size_t)(nBase + row) * K + k0 + c4);
            As[row][c4 + 0] = __uint_as_float(f2tf32(av.x));
            As[row][c4 + 1] = __uint_as_float(f2tf32(av.y));
            As[row][c4 + 2] = __uint_as_float(f2tf32(av.z));
            As[row][c4 + 3] = __uint_as_float(f2tf32(av.w));
            Bs[row][c4 + 0] = __uint_as_float(f2tf32(bv.x));
            Bs[row][c4 + 1] = __uint_as_float(f2tf32(bv.y));
            Bs[row][c4 + 2] = __uint_as_float(f2tf32(bv.z));
            Bs[row][c4 + 3] = __uint_as_float(f2tf32(bv.w));
        }
        __syncthreads();

        // ---- compute: 2 k-steps of 8 ----
#pragma unroll
        for (int ks = 0; ks < 2; ks++) {
            const int kb = ks * 8;
            uint32_t af[2][4];
#pragma unroll
            for (int mt = 0; mt < 2; mt++) {
                int r0 = warpM + mt * 16 + g;
                af[mt][0] = __float_as_uint(As[r0    ][kb + t    ]);
                af[mt][1] = __float_as_uint(As[r0 + 8][kb + t    ]);
                af[mt][2] = __float_as_uint(As[r0    ][kb + t + 4]);
                af[mt][3] = __float_as_uint(As[r0 + 8][kb + t + 4]);
            }
            uint32_t bf[8][2];
#pragma unroll
            for (int nt = 0; nt < 8; nt++) {
                int c = warpN + nt * 8 + g;
                bf[nt][0] = __float_as_uint(Bs[c][kb + t    ]);
                bf[nt][1] = __float_as_uint(Bs[c][kb + t + 4]);
            }
#pragma unroll
            for (int mt = 0; mt < 2; mt++)
#pragma unroll
                for (int nt = 0; nt < 8; nt++) {
                    asm volatile(
                        "mma.sync.aligned.m16n8k8.row.col.f32.tf32.tf32.f32 "
                        "{%0,%1,%2,%3}, {%4,%5,%6,%7}, {%8,%9}, {%0,%1,%2,%3};"
                        : "+f"(acc[mt][nt][0]), "+f"(acc[mt][nt][1]),
                          "+f"(acc[mt][nt][2]), "+f"(acc[mt][nt][3])
                        : "r"(af[mt][0]), "r"(af[mt][1]), "r"(af[mt][2]), "r"(af[mt][3]),
                          "r"(bf[nt][0]), "r"(bf[nt][1]));
                }
        }
    }

    // ---- epilogue: add bias, store ----
#pragma unroll
    for (int mt = 0; mt < 2; mt++) {
        int row = mBase + warpM + mt * 16 + g;
#pragma unroll
        for (int nt = 0; nt < 8; nt++) {
            int col = nBase + warpN + nt * 8 + 2 * t;
            float b0 = bias[col], b1 = bias[col + 1];
            float2 v0 = make_float2(acc[mt][nt][0] + b0, acc[mt][nt][1] + b1);
            float2 v1 = make_float2(acc[mt][nt][2] + b0, acc[mt][nt][3] + b1);
            *reinterpret_cast<float2*>(C + (size_t)row * N + col) = v0;
            *reinterpret_cast<float2*>(C + (size_t)(row + 8) * N + col) = v1;
        }
    }
}

// ---------------------------------------------------------------------------
// Scan stage 1: per-(b, chunk, n) compute chunk-end state only (read-only pass)
// ---------------------------------------------------------------------------
__global__ __launch_bounds__(256) void scan_ends_kernel(const float* __restrict__ log_A)
{
    int idx = blockIdx.x * blockDim.x + threadIdx.x;   // B*NCHUNK*N threads
    int n = idx & (N_STATE - 1);
    int c = (idx / N_STATE) & (NCHUNK - 1);
    int b = idx / (N_STATE * NCHUNK);
    if (b >= BATCH) return;

    const float Av = sigmoidf_(log_A[n]);
    size_t base = ((size_t)b * SEQ_T + (size_t)c * CHUNK) * N_STATE + n;
    float h = 0.0f;
#pragma unroll 4
    for (int tt = 0; tt < CHUNK; tt++)
        h = fmaf(Av, h, g_bx[base + (size_t)tt * N_STATE]);
    g_end[((size_t)b * NCHUNK + c) * N_STATE + n] = h;
}

// ---------------------------------------------------------------------------
// Scan stage 2: recompute carry from chunk ends inline, then final inclusive
// scan of the chunk written in place.
// ---------------------------------------------------------------------------
__global__ __launch_bounds__(256) void scan_apply_kernel(const float* __restrict__ log_A)
{
    int idx = blockIdx.x * blockDim.x + threadIdx.x;   // B*NCHUNK*N threads
    int n = idx & (N_STATE - 1);
    int c = (idx / N_STATE) & (NCHUNK - 1);
    int b = idx / (N_STATE * NCHUNK);
    if (b >= BATCH) return;

    const float Av = sigmoidf_(log_A[n]);
    float aL = Av;                          // A^128 by squaring
#pragma unroll
    for (int s = 0; s < 7; s++) aL = aL * aL;

    float E = 0.0f;                         // carry into chunk c
    for (int cp = 0; cp < c; cp++)
        E = fmaf(aL, E, g_end[((size_t)b * NCHUNK + cp) * N_STATE + n]);

    size_t base = ((size_t)b * SEQ_T + (size_t)c * CHUNK) * N_STATE + n;
    float h = E;
#pragma unroll 4
    for (int tt = 0; tt < CHUNK; tt++) {
        size_t off = base + (size_t)tt * N_STATE;
        h = fmaf(Av, h, g_bx[off]);
        g_bx[off] = h;
    }
}

// ---------------------------------------------------------------------------
// Launch
// ---------------------------------------------------------------------------
extern "C" void kernel_launch(void* const* d_in, const int* in_sizes, int n_in,
                              void* d_out, int out_size)
{
    const float* x    = (const float*)d_in[0];   // [8, 2048, 1024]
    const float* logA = (const float*)d_in[1];   // [1024]
    const float* B_w  = (const float*)d_in[2];   // [1024, 1024] (N, D)
    const float* B_b  = (const float*)d_in[3];   // [1024]
    const float* C_w  = (const float*)d_in[4];   // [1024, 1024] (D, N)
    const float* C_b  = (const float*)d_in[5];   // [1024]
    float* y = (float*)d_out;                    // [8, 2048, 1024]

    float* bx;
    cudaGetSymbolAddress((void**)&bx, g_bx);

    // GEMM1: B_x = x @ B_w^T + B_b   (tensor cores, tf32)
    {
        dim3 grid(N_STATE / 128, MROWS / 128);
        gemm_tf32_tn<<<grid, 256>>>(x, B_w, B_b, bx, MROWS, N_STATE, D_MODEL);
    }

    // Scan (chunked, 2 passes)
    {
        int total = BATCH * NCHUNK * N_STATE;
        scan_ends_kernel<<<total / 256, 256>>>(logA);
        scan_apply_kernel<<<total / 256, 256>>>(logA);
    }

    // GEMM2: y = h @ C_w^T + C_b    (tensor cores, tf32)
    {
        dim3 grid(D_MODEL / 128, MROWS / 128);
        gemm_tf32_tn<<<grid, 256>>>(bx, C_w, C_b, y, MROWS, D_MODEL, N_STATE);
    }
}

// round 6
// speedup vs baseline: 2.2408x; 1.1073x over previous
#include <cuda_runtime.h>
#include <math.h>
#include <stdint.h>

// ---------------------------------------------------------------------------
// Problem shape (fixed)
// ---------------------------------------------------------------------------
constexpr int BATCH = 8;
constexpr int SEQ_T = 2048;
constexpr int D_MODEL = 1024;
constexpr int N_STATE = 1024;
constexpr int MROWS = BATCH * SEQ_T;      // 16384
constexpr int KDIM = 1024;
constexpr int CHUNK = 128;
constexpr int NCHUNK = SEQ_T / CHUNK;     // 16

// Scratch (no cudaMalloc allowed)
__device__ float g_bx[MROWS * N_STATE];                 // B_x -> h (rna'd by scan)
__device__ float g_xc[MROWS * D_MODEL];                 // rna(x)
__device__ float g_w1[N_STATE * D_MODEL];               // rna(B_w)
__device__ float g_w2[D_MODEL * N_STATE];               // rna(C_w)
__device__ float g_end[BATCH * NCHUNK * N_STATE];       // chunk-end states

__device__ __forceinline__ float sigmoidf_(float x) {
    return 1.0f / (1.0f + __expf(-x));
}
__device__ __forceinline__ uint32_t f2tf32(float x) {
    uint32_t r;
    asm("cvt.rna.tf32.f32 %0, %1;" : "=r"(r) : "f"(x));
    return r;
}
__device__ __forceinline__ uint32_t smem_u32(const void* p) {
    uint32_t a;
    asm("{ .reg .u64 t; cvta.to.shared.u64 t, %1; cvt.u32.u64 %0, t; }" : "=r"(a) : "l"(p));
    return a;
}

#define CP_ASYNC16(dst, src) \
    asm volatile("cp.async.cg.shared.global [%0], [%1], 16;" :: "r"(dst), "l"(src))
#define CP_COMMIT() asm volatile("cp.async.commit_group;" ::: "memory")
#define CP_WAIT1()  asm volatile("cp.async.wait_group 1;" ::: "memory")

#define LDSM_X4(r0, r1, r2, r3, addr) \
    asm volatile("ldmatrix.sync.aligned.m8n8.x4.shared.b16 {%0,%1,%2,%3}, [%4];" \
        : "=r"(r0), "=r"(r1), "=r"(r2), "=r"(r3) : "r"(addr))

// ---------------------------------------------------------------------------
// TF32 mma.sync GEMM: C[M,N=1024] = A[M,K]*B[N,K]^T + bias
// CTA tile 128x128x32, 4 warps (warp tile 64x64), cp.async 2-stage pipeline,
// SW128-swizzled smem, ldmatrix fragment loads. Operands pre-rounded to tf32.
// ---------------------------------------------------------------------------
constexpr int BM = 128, BN = 128, BK = 32;
constexpr int A_BYTES = BM * 128;                 // 16 KB (32 floats/row = 128B)
constexpr int B_BYTES = BN * 128;                 // 16 KB
constexpr int STAGE_BYTES = A_BYTES + B_BYTES;    // 32 KB
constexpr int SMEM_GEMM_TOTAL = 2 * STAGE_BYTES;  // 64 KB
constexpr int NITER = KDIM / BK;                  // 32

__global__ __launch_bounds__(128, 2) void gemm_tc_tf32(
    const float* __restrict__ A, const float* __restrict__ Bw,
    const float* __restrict__ bias, float* __restrict__ C)
{
    extern __shared__ char smem[];
    const uint32_t sb = smem_u32(smem);
    const int tid = threadIdx.x;
    const int wid = tid >> 5;
    const int lane = tid & 31;
    const int g = lane >> 2;          // 0..7
    const int t = lane & 3;           // 0..3
    const int mBase = blockIdx.y * BM;
    const int nBase = blockIdx.x * BN;
    const int warpM = (wid >> 1) * 64;
    const int warpN = (wid & 1) * 64;

    // ldmatrix lane roles
    const int j = lane >> 3;          // matrix index 0..3
    const int r = lane & 7;           // row within matrix

    // Per-lane precomputed ldmatrix address parts.
    // A (per mt): row = warpM + mt*16 + (j&1)*8 + r ; k-chunk add = j>>1
    uint32_t aRow[4], aXor[4];
#pragma unroll
    for (int mt = 0; mt < 4; mt++) {
        int row = warpM + mt * 16 + (j & 1) * 8 + r;
        aRow[mt] = (uint32_t)row * 128u;
        aXor[mt] = (uint32_t)(row & 7) << 4;
    }
    const uint32_t aKj = (uint32_t)(j >> 1);
    // B (per ntp): row = warpN + ntp*16 + (j>>1)*8 + r ; k-chunk add = j&1
    uint32_t bRow[4], bXor[4];
#pragma unroll
    for (int ntp = 0; ntp < 4; ntp++) {
        int row = warpN + ntp * 16 + (j >> 1) * 8 + r;
        bRow[ntp] = (uint32_t)row * 128u;
        bXor[ntp] = (uint32_t)(row & 7) << 4;
    }
    const uint32_t bKj = (uint32_t)(j & 1);

    float acc[4][8][4];
#pragma unroll
    for (int mt = 0; mt < 4; mt++)
#pragma unroll
        for (int nt = 0; nt < 8; nt++)
#pragma unroll
            for (int q = 0; q < 4; q++) acc[mt][nt][q] = 0.0f;

    // ---- producer: fill stage s with K-chunk at k0 (each thread: one A row
    //      + one B row, 8 x 16B cp.async each, SW128 swizzle) ----
    auto fill = [&](int s, int k0) {
        uint32_t aB = sb + (uint32_t)s * STAGE_BYTES;
        uint32_t bB = aB + A_BYTES;
        const float* asrc = A + (size_t)(mBase + tid) * KDIM + k0;
        const float* bsrc = Bw + (size_t)(nBase + tid) * KDIM + k0;
        uint32_t rowp = (uint32_t)tid * 128u;
        uint32_t xv = (uint32_t)(tid & 7) << 4;
#pragma unroll
        for (int c = 0; c < 8; c++) {
            uint32_t co = ((uint32_t)c << 4) ^ xv;
            CP_ASYNC16(aB + rowp + co, asrc + c * 4);
            CP_ASYNC16(bB + rowp + co, bsrc + c * 4);
        }
    };

    fill(0, 0);  CP_COMMIT();
    fill(1, BK); CP_COMMIT();

    for (int i = 0; i < NITER; i++) {
        CP_WAIT1();
        __syncthreads();

        const uint32_t aBase = sb + (uint32_t)(i & 1) * STAGE_BYTES;
        const uint32_t bBase = aBase + A_BYTES;

#pragma unroll
        for (int ks = 0; ks < 4; ks++) {
            const uint32_t kc0 = (uint32_t)ks * 2u;
            uint32_t af[4][4];
#pragma unroll
            for (int mt = 0; mt < 4; mt++) {
                uint32_t addr = aBase + aRow[mt] + ((((kc0 + aKj) << 4)) ^ aXor[mt]);
                LDSM_X4(af[mt][0], af[mt][1], af[mt][2], af[mt][3], addr);
            }
            uint32_t bf[8][2];
#pragma unroll
            for (int ntp = 0; ntp < 4; ntp++) {
                uint32_t addr = bBase + bRow[ntp] + ((((kc0 + bKj) << 4)) ^ bXor[ntp]);
                LDSM_X4(bf[2 * ntp][0], bf[2 * ntp][1],
                        bf[2 * ntp + 1][0], bf[2 * ntp + 1][1], addr);
            }
#pragma unroll
            for (int mt = 0; mt < 4; mt++)
#pragma unroll
                for (int nt = 0; nt < 8; nt++) {
                    asm volatile(
                        "mma.sync.aligned.m16n8k8.row.col.f32.tf32.tf32.f32 "
                        "{%0,%1,%2,%3}, {%4,%5,%6,%7}, {%8,%9}, {%0,%1,%2,%3};"
                        : "+f"(acc[mt][nt][0]), "+f"(acc[mt][nt][1]),
                          "+f"(acc[mt][nt][2]), "+f"(acc[mt][nt][3])
                        : "r"(af[mt][0]), "r"(af[mt][1]), "r"(af[mt][2]), "r"(af[mt][3]),
                          "r"(bf[nt][0]), "r"(bf[nt][1]));
                }
        }

        __syncthreads();
        int nk = (i + 2) * BK;
        if (nk < KDIM) fill(i & 1, nk);
        CP_COMMIT();
    }

    // ---- epilogue: add bias, store ----
#pragma unroll
    for (int mt = 0; mt < 4; mt++) {
        int row0 = mBase + warpM + mt * 16 + g;
#pragma unroll
        for (int nt = 0; nt < 8; nt++) {
            int col = nBase + warpN + nt * 8 + 2 * t;
            float b0 = bias[col], b1 = bias[col + 1];
            float2 v0 = make_float2(acc[mt][nt][0] + b0, acc[mt][nt][1] + b1);
            float2 v1 = make_float2(acc[mt][nt][2] + b0, acc[mt][nt][3] + b1);
            *reinterpret_cast<float2*>(C + (size_t)row0 * 1024 + col) = v0;
            *reinterpret_cast<float2*>(C + (size_t)(row0 + 8) * 1024 + col) = v1;
        }
    }
}

// ---------------------------------------------------------------------------
// rna(tf32) conversion pass
// ---------------------------------------------------------------------------
__global__ __launch_bounds__(256) void conv_rna_kernel(
    const float* __restrict__ src, float* __restrict__ dst, int n4)
{
    int i = blockIdx.x * blockDim.x + threadIdx.x;
    if (i >= n4) return;
    float4 v = reinterpret_cast<const float4*>(src)[i];
    v.x = __uint_as_float(f2tf32(v.x));
    v.y = __uint_as_float(f2tf32(v.y));
    v.z = __uint_as_float(f2tf32(v.z));
    v.w = __uint_as_float(f2tf32(v.w));
    reinterpret_cast<float4*>(dst)[i] = v;
}

// ---------------------------------------------------------------------------
// Scan stage 1: per-(b, chunk, n) chunk-end state (read-only pass)
// ---------------------------------------------------------------------------
__global__ __launch_bounds__(256) void scan_ends_kernel(const float* __restrict__ log_A)
{
    int idx = blockIdx.x * blockDim.x + threadIdx.x;
    int n = idx & (N_STATE - 1);
    int c = (idx / N_STATE) & (NCHUNK - 1);
    int b = idx / (N_STATE * NCHUNK);
    if (b >= BATCH) return;

    const float Av = sigmoidf_(log_A[n]);
    size_t base = ((size_t)b * SEQ_T + (size_t)c * CHUNK) * N_STATE + n;
    float h = 0.0f;
#pragma unroll 4
    for (int tt = 0; tt < CHUNK; tt++)
        h = fmaf(Av, h, g_bx[base + (size_t)tt * N_STATE]);
    g_end[((size_t)b * NCHUNK + c) * N_STATE + n] = h;
}

// ---------------------------------------------------------------------------
// Scan stage 2: carry from ends, final inclusive scan; h written rna-rounded
// (it is GEMM2's A operand).
// ---------------------------------------------------------------------------
__global__ __launch_bounds__(256) void scan_apply_kernel(const float* __restrict__ log_A)
{
    int idx = blockIdx.x * blockDim.x + threadIdx.x;
    int n = idx & (N_STATE - 1);
    int c = (idx / N_STATE) & (NCHUNK - 1);
    int b = idx / (N_STATE * NCHUNK);
    if (b >= BATCH) return;

    const float Av = sigmoidf_(log_A[n]);
    float aL = Av;
#pragma unroll
    for (int s = 0; s < 7; s++) aL = aL * aL;

    float E = 0.0f;
    for (int cp = 0; cp < c; cp++)
        E = fmaf(aL, E, g_end[((size_t)b * NCHUNK + cp) * N_STATE + n]);

    size_t base = ((size_t)b * SEQ_T + (size_t)c * CHUNK) * N_STATE + n;
    float h = E;
#pragma unroll 4
    for (int tt = 0; tt < CHUNK; tt++) {
        size_t off = base + (size_t)tt * N_STATE;
        h = fmaf(Av, h, g_bx[off]);
        g_bx[off] = __uint_as_float(f2tf32(h));
    }
}

// ---------------------------------------------------------------------------
// Launch
// ---------------------------------------------------------------------------
extern "C" void kernel_launch(void* const* d_in, const int* in_sizes, int n_in,
                              void* d_out, int out_size)
{
    const float* x    = (const float*)d_in[0];   // [8, 2048, 1024]
    const float* logA = (const float*)d_in[1];   // [1024]
    const float* B_w  = (const float*)d_in[2];   // [1024, 1024] (N, D)
    const float* B_b  = (const float*)d_in[3];   // [1024]
    const float* C_w  = (const float*)d_in[4];   // [1024, 1024] (D, N)
    const float* C_b  = (const float*)d_in[5];   // [1024]
    float* y = (float*)d_out;                    // [8, 2048, 1024]

    float *bx, *xc, *w1, *w2;
    cudaGetSymbolAddress((void**)&bx, g_bx);
    cudaGetSymbolAddress((void**)&xc, g_xc);
    cudaGetSymbolAddress((void**)&w1, g_w1);
    cudaGetSymbolAddress((void**)&w2, g_w2);

    cudaFuncSetAttribute(gemm_tc_tf32, cudaFuncAttributeMaxDynamicSharedMemorySize,
                         SMEM_GEMM_TOTAL);

    // rna-round operands for tf32 MMA
    {
        int n4x = MROWS * D_MODEL / 4;
        conv_rna_kernel<<<n4x / 256, 256>>>(x, xc, n4x);
        int n4w = N_STATE * D_MODEL / 4;
        conv_rna_kernel<<<n4w / 256, 256>>>(B_w, w1, n4w);
        conv_rna_kernel<<<n4w / 256, 256>>>(C_w, w2, n4w);
    }

    // GEMM1: B_x = x @ B_w^T + B_b
    {
        dim3 grid(N_STATE / BN, MROWS / BM);   // (8, 128)
        gemm_tc_tf32<<<grid, 128, SMEM_GEMM_TOTAL>>>(xc, w1, B_b, bx);
    }

    // Scan (chunked, 2 passes; h written rna-rounded)
    {
        int total = BATCH * NCHUNK * N_STATE;
        scan_ends_kernel<<<total / 256, 256>>>(logA);
        scan_apply_kernel<<<total / 256, 256>>>(logA);
    }

    // GEMM2: y = h @ C_w^T + C_b
    {
        dim3 grid(D_MODEL / BN, MROWS / BM);   // (8, 128)
        gemm_tc_tf32<<<grid, 128, SMEM_GEMM_TOTAL>>>(bx, w2, C_b, y);
    }
}